// round 2
// baseline (speedup 1.0000x reference)
#include <cuda_runtime.h>
#include <math.h>

#define MTOT 8192
#define CDIM 1024
#define NHEAD 16
#define DH 64
#define TSEQ 2048

// Scratch (allocation-free rule: __device__ globals)
__device__ float g_Q[(size_t)MTOT * CDIM];
__device__ float g_V[(size_t)MTOT * CDIM];
__device__ float g_O[(size_t)MTOT * CDIM];

// ---------------------------------------------------------------------------
// C[M,N] = A[M,K] @ B[N,K]^T   (both operands K-major, coalesced loads)
// 64x64 block tile, BK=16, 256 threads, 4x4 accumulators per thread.
// Smem stored K-transposed so fragment reads are float4 / conflict-free.
// ---------------------------------------------------------------------------
#define BM 64
#define BN 64
#define BK 16

__global__ __launch_bounds__(256) void gemm_abt(
    const float* __restrict__ A, const float* __restrict__ B,
    float* __restrict__ C, int M, int N, int K)
{
    __shared__ float As[BK][BM + 4];
    __shared__ float Bs[BK][BN + 4];

    const int tid = threadIdx.x;
    const int tx = tid & 15;       // 0..15  -> N direction
    const int ty = tid >> 4;       // 0..15  -> M direction
    const int row0 = blockIdx.y * BM;
    const int col0 = blockIdx.x * BN;

    const int lr = tid >> 2;          // 0..63 tile row for loads
    const int lc = (tid & 3) << 2;    // 0,4,8,12 k-offset for loads

    float acc[4][4];
#pragma unroll
    for (int i = 0; i < 4; i++)
#pragma unroll
        for (int j = 0; j < 4; j++) acc[i][j] = 0.f;

    const float* Aptr = A + (size_t)(row0 + lr) * K + lc;
    const float* Bptr = B + (size_t)(col0 + lr) * K + lc;

    for (int k0 = 0; k0 < K; k0 += BK) {
        float4 a4 = *(const float4*)(Aptr + k0);
        float4 b4 = *(const float4*)(Bptr + k0);
        As[lc + 0][lr] = a4.x; As[lc + 1][lr] = a4.y;
        As[lc + 2][lr] = a4.z; As[lc + 3][lr] = a4.w;
        Bs[lc + 0][lr] = b4.x; Bs[lc + 1][lr] = b4.y;
        Bs[lc + 2][lr] = b4.z; Bs[lc + 3][lr] = b4.w;
        __syncthreads();
#pragma unroll
        for (int kk = 0; kk < BK; kk++) {
            float4 av = *(const float4*)(&As[kk][ty << 2]);
            float4 bv = *(const float4*)(&Bs[kk][tx << 2]);
            float a[4] = {av.x, av.y, av.z, av.w};
            float b[4] = {bv.x, bv.y, bv.z, bv.w};
#pragma unroll
            for (int i = 0; i < 4; i++)
#pragma unroll
                for (int j = 0; j < 4; j++)
                    acc[i][j] = fmaf(a[i], b[j], acc[i][j]);
        }
        __syncthreads();
    }

#pragma unroll
    for (int i = 0; i < 4; i++) {
        float4 o4 = make_float4(acc[i][0], acc[i][1], acc[i][2], acc[i][3]);
        *(float4*)(C + (size_t)(row0 + (ty << 2) + i) * N + col0 + (tx << 2)) = o4;
    }
}

// ---------------------------------------------------------------------------
// Flash attention, fp32. One block = 64 queries of one (b,h).
// K tile == Q tile data (reference bug: K uses W_q). Causal.
// Smem: Qs/Ks transposed [d][i] for float4 fragment reads; Vs natural [j][d];
// Ps [j][i] with odd-ish pad (scalar broadcast reads).
// ---------------------------------------------------------------------------
#define QPAD 68
#define PPAD 65
#define ATT_SMEM ((3 * 64 * QPAD + 64 * PPAD) * 4)  // 68864 bytes

__global__ __launch_bounds__(256) void attn_kernel(
    const float* __restrict__ Q, const float* __restrict__ V,
    float* __restrict__ O)
{
    extern __shared__ float sm[];
    float* Qs = sm;                 // [64][QPAD] : [d][i]
    float* Ks = Qs + 64 * QPAD;     // [64][QPAD] : [d][j]
    float* Vs = Ks + 64 * QPAD;     // [64][QPAD] : [j][d]
    float* Ps = Vs + 64 * QPAD;     // [64][PPAD] : [j][i]

    const int tid = threadIdx.x;
    const int tx = tid & 15;        // key / d-out direction
    const int ty = tid >> 4;        // query direction
    const int qb = blockIdx.x;      // 0..31
    const int bh = blockIdx.y;      // 0..63
    const int b = bh >> 4, h = bh & 15;
    const int t0 = qb * 64;

    const float* Qbase = Q + (size_t)b * TSEQ * CDIM + h * DH;
    const float* Vbase = V + (size_t)b * TSEQ * CDIM + h * DH;

    // Load Q tile transposed: Qs[d][i]
#pragma unroll
    for (int p = 0; p < 4; p++) {
        int i = p * 16 + ty;
        int d = tx << 2;
        float4 q4 = *(const float4*)(Qbase + (size_t)(t0 + i) * CDIM + d);
        Qs[(d + 0) * QPAD + i] = q4.x;
        Qs[(d + 1) * QPAD + i] = q4.y;
        Qs[(d + 2) * QPAD + i] = q4.z;
        Qs[(d + 3) * QPAD + i] = q4.w;
    }

    float m[4], l[4], o[4][4];
#pragma unroll
    for (int i = 0; i < 4; i++) {
        m[i] = -1e30f; l[i] = 0.f;
#pragma unroll
        for (int j = 0; j < 4; j++) o[i][j] = 0.f;
    }

    const float scale = 0.125f;  // 1/sqrt(64)

    for (int jt = 0; jt <= qb; jt++) {
        const int j0 = jt * 64;
        __syncthreads();  // protect Qs (iter 0) and Ks/Vs/Ps reuse
        // Load K (= Q rows j0..) transposed and V natural
#pragma unroll
        for (int p = 0; p < 4; p++) {
            int j = p * 16 + ty;
            int d = tx << 2;
            float4 k4 = *(const float4*)(Qbase + (size_t)(j0 + j) * CDIM + d);
            Ks[(d + 0) * QPAD + j] = k4.x;
            Ks[(d + 1) * QPAD + j] = k4.y;
            Ks[(d + 2) * QPAD + j] = k4.z;
            Ks[(d + 3) * QPAD + j] = k4.w;
            float4 v4 = *(const float4*)(Vbase + (size_t)(j0 + j) * CDIM + d);
            *(float4*)(Vs + j * QPAD + d) = v4;
        }
        __syncthreads();

        // S = Q K^T
        float s[4][4];
#pragma unroll
        for (int i = 0; i < 4; i++)
#pragma unroll
            for (int j = 0; j < 4; j++) s[i][j] = 0.f;
#pragma unroll 8
        for (int d = 0; d < 64; d++) {
            float4 av = *(const float4*)(Qs + d * QPAD + (ty << 2));
            float4 bv = *(const float4*)(Ks + d * QPAD + (tx << 2));
            float a[4] = {av.x, av.y, av.z, av.w};
            float bb[4] = {bv.x, bv.y, bv.z, bv.w};
#pragma unroll
            for (int i = 0; i < 4; i++)
#pragma unroll
                for (int j = 0; j < 4; j++)
                    s[i][j] = fmaf(a[i], bb[j], s[i][j]);
        }

        // Causal mask only needed on the diagonal tile
        if (jt == qb) {
#pragma unroll
            for (int ii = 0; ii < 4; ii++)
#pragma unroll
                for (int jj = 0; jj < 4; jj++)
                    if ((tx << 2) + jj > (ty << 2) + ii) s[ii][jj] = -1e38f;
        }

        // Online softmax per row (row owned by 16 lanes: tx)
#pragma unroll
        for (int ii = 0; ii < 4; ii++) {
            float mx = -1e30f;
#pragma unroll
            for (int jj = 0; jj < 4; jj++) {
                s[ii][jj] = (s[ii][jj] <= -1e37f) ? -1e30f : s[ii][jj] * scale;
                mx = fmaxf(mx, s[ii][jj]);
            }
#pragma unroll
            for (int off = 8; off >= 1; off >>= 1)
                mx = fmaxf(mx, __shfl_xor_sync(0xffffffffu, mx, off));
            float mnew = fmaxf(m[ii], mx);
            float alpha = __expf(m[ii] - mnew);
            m[ii] = mnew;
            float p[4], psum = 0.f;
#pragma unroll
            for (int jj = 0; jj < 4; jj++) {
                p[jj] = __expf(s[ii][jj] - mnew);
                psum += p[jj];
            }
#pragma unroll
            for (int off = 8; off >= 1; off >>= 1)
                psum += __shfl_xor_sync(0xffffffffu, psum, off);
            l[ii] = l[ii] * alpha + psum;
#pragma unroll
            for (int jj = 0; jj < 4; jj++) o[ii][jj] *= alpha;
#pragma unroll
            for (int jj = 0; jj < 4; jj++)
                Ps[((tx << 2) + jj) * PPAD + (ty << 2) + ii] = p[jj];
        }
        __syncthreads();

        // O += P @ V
#pragma unroll 8
        for (int j = 0; j < 64; j++) {
            float a[4];
#pragma unroll
            for (int ii = 0; ii < 4; ii++)
                a[ii] = Ps[j * PPAD + (ty << 2) + ii];
            float4 bv = *(const float4*)(Vs + j * QPAD + (tx << 2));
            float bb[4] = {bv.x, bv.y, bv.z, bv.w};
#pragma unroll
            for (int ii = 0; ii < 4; ii++)
#pragma unroll
                for (int jj = 0; jj < 4; jj++)
                    o[ii][jj] = fmaf(a[ii], bb[jj], o[ii][jj]);
        }
    }

    // Epilogue: normalize and write (merged-head layout column h*64)
    float* Obase = O + (size_t)b * TSEQ * CDIM + h * DH;
#pragma unroll
    for (int ii = 0; ii < 4; ii++) {
        float inv = 1.0f / l[ii];
        float4 o4 = make_float4(o[ii][0] * inv, o[ii][1] * inv,
                                o[ii][2] * inv, o[ii][3] * inv);
        *(float4*)(Obase + (size_t)(t0 + (ty << 2) + ii) * CDIM + (tx << 2)) = o4;
    }
}

// ---------------------------------------------------------------------------
extern "C" void kernel_launch(void* const* d_in, const int* in_sizes, int n_in,
                              void* d_out, int out_size)
{
    (void)in_sizes; (void)n_in; (void)out_size;
    const float* x  = (const float*)d_in[0];
    const float* Wq = (const float*)d_in[1];
    // d_in[2] (W_k) intentionally unused: reference computes K with W_q
    const float* Wv = (const float*)d_in[3];
    const float* Wo = (const float*)d_in[4];
    float* out = (float*)d_out;

    float *Qb, *Vb, *Ob;
    cudaGetSymbolAddress((void**)&Qb, g_Q);
    cudaGetSymbolAddress((void**)&Vb, g_V);
    cudaGetSymbolAddress((void**)&Ob, g_O);

    dim3 gg(CDIM / BN, MTOT / BM);  // (16, 128)
    gemm_abt<<<gg, 256>>>(x, Wq, Qb, MTOT, CDIM, CDIM);
    gemm_abt<<<gg, 256>>>(x, Wv, Vb, MTOT, CDIM, CDIM);

    cudaFuncSetAttribute(attn_kernel, cudaFuncAttributeMaxDynamicSharedMemorySize,
                         ATT_SMEM);
    attn_kernel<<<dim3(TSEQ / 64, 4 * NHEAD), 256, ATT_SMEM>>>(Qb, Vb, Ob);

    gemm_abt<<<gg, 256>>>(Ob, Wo, out, MTOT, CDIM, CDIM);
}

// round 5
// speedup vs baseline: 1.4861x; 1.4861x over previous
#include <cuda_runtime.h>
#include <math.h>
#include <stdint.h>

#define MTOT 8192
#define CDIM 1024
#define NHEAD 16
#define DH 64
#define TSEQ 2048

// Scratch (allocation-free rule: __device__ globals)
__device__ float g_Q[(size_t)MTOT * CDIM];
__device__ float g_V[(size_t)MTOT * CDIM];
__device__ float g_O[(size_t)MTOT * CDIM];

__device__ __forceinline__ float f2tf32f(float v) {
    uint32_t r;
    asm("cvt.rna.tf32.f32 %0, %1;" : "=r"(r) : "f"(v));
    return __uint_as_float(r);
}

// ===========================================================================
// tf32 mma.sync GEMM:  C[M,N] = A[M,K] @ B[N,K]^T   (K = N = CDIM)
// CTA tile 128x128, BK=32, 256 threads = 8 warps, warp tile 64x32.
// SMEM holds operands PRE-PERMUTED into m16n8k8 fragment order:
//   A buffer: [m_tile(8)][ks(4)][lane(32)][4 regs]  -> ld.shared.v4
//   B buffer: [n_tile(16)][ks(4)][lane(32)][2 regs] -> ld.shared.v2
// Double buffered; global prefetch in registers; 1 syncthreads per chunk.
// ===========================================================================
#define NCH (CDIM / 32)          // 32 chunks
#define GEMM_SMEM (4 * 4096 * 4) // 64 KB

__global__ __launch_bounds__(256) void gemm_mma(
    const float* __restrict__ A, const float* __restrict__ B,
    float* __restrict__ C)
{
    extern __shared__ float smem[];
    // Ap[buf] = smem + buf*4096 ; Bp[buf] = smem + 8192 + buf*4096
    const int tid = threadIdx.x;
    const int lane = tid & 31;
    const int wid = tid >> 5;
    const int wm = wid & 1;      // 0..1  (M direction, 64 rows each)
    const int wn = wid >> 1;     // 0..3  (N direction, 32 cols each)
    const int row0 = blockIdx.y * 128;
    const int col0 = blockIdx.x * 128;

    float acc[4][4][4];
#pragma unroll
    for (int i = 0; i < 4; i++)
#pragma unroll
        for (int j = 0; j < 4; j++)
#pragma unroll
            for (int r = 0; r < 4; r++) acc[i][j][r] = 0.f;

    // Loader geometry: thread covers rows lrow+32i (i<4), k-span [lk, lk+4)
    const int lrow = tid >> 3;          // 0..31
    const int lk   = (tid & 7) << 2;    // 0,4,...,28
    const int ksA  = lk >> 3;           // fragment k-step (0..3)
    const int regHi = (lk >> 2) & 1;    // high half of k within step

    const float* Ab = A + (size_t)(row0 + lrow) * CDIM + lk;
    const float* Bb = B + (size_t)(col0 + lrow) * CDIM + lk;

    float4 ra[4], rb[4];

    // ---- store staged registers into permuted smem buffer ----
#define STORE_CHUNK(buf) do {                                                  \
    float* Abuf = smem + (buf) * 4096;                                         \
    float* Bbuf = smem + 8192 + (buf) * 4096;                                  \
    _Pragma("unroll")                                                          \
    for (int i = 0; i < 4; i++) {                                              \
        int r = i * 32 + lrow;                                                 \
        int mt = r >> 4, rm = r & 15;                                          \
        float* da = &Abuf[(((mt * 4 + ksA) * 32) + ((rm & 7) << 2)) * 4        \
                          + ((rm >> 3) | (regHi << 1))];                       \
        da[0]  = f2tf32f(ra[i].x); da[4]  = f2tf32f(ra[i].y);                  \
        da[8]  = f2tf32f(ra[i].z); da[12] = f2tf32f(ra[i].w);                  \
        int nt = r >> 3, nn = r & 7;                                           \
        float* db = &Bbuf[(((nt * 4 + ksA) * 32) + (nn << 2)) * 2 + regHi];    \
        db[0] = f2tf32f(rb[i].x); db[2] = f2tf32f(rb[i].y);                    \
        db[4] = f2tf32f(rb[i].z); db[6] = f2tf32f(rb[i].w);                    \
    }                                                                          \
} while (0)

    // Prologue: chunk 0
#pragma unroll
    for (int i = 0; i < 4; i++) {
        ra[i] = *(const float4*)(Ab + (size_t)(i * 32) * CDIM);
        rb[i] = *(const float4*)(Bb + (size_t)(i * 32) * CDIM);
    }
    STORE_CHUNK(0);
    __syncthreads();

    for (int c = 0; c < NCH; c++) {
        const int cur = c & 1;
        if (c + 1 < NCH) {
#pragma unroll
            for (int i = 0; i < 4; i++) {
                ra[i] = *(const float4*)(Ab + (size_t)(i * 32) * CDIM + (c + 1) * 32);
                rb[i] = *(const float4*)(Bb + (size_t)(i * 32) * CDIM + (c + 1) * 32);
            }
        }

        const float* Abuf = smem + cur * 4096;
        const float* Bbuf = smem + 8192 + cur * 4096;
#pragma unroll
        for (int ks = 0; ks < 4; ks++) {
            uint4 af[4]; uint2 bf[4];
#pragma unroll
            for (int i = 0; i < 4; i++)
                af[i] = *(const uint4*)&Abuf[(((wm * 4 + i) * 4 + ks) * 32 + lane) * 4];
#pragma unroll
            for (int j = 0; j < 4; j++)
                bf[j] = *(const uint2*)&Bbuf[(((wn * 4 + j) * 4 + ks) * 32 + lane) * 2];
#pragma unroll
            for (int i = 0; i < 4; i++)
#pragma unroll
                for (int j = 0; j < 4; j++)
                    asm volatile(
                        "mma.sync.aligned.m16n8k8.row.col.f32.tf32.tf32.f32 "
                        "{%0,%1,%2,%3}, {%4,%5,%6,%7}, {%8,%9}, {%0,%1,%2,%3};"
                        : "+f"(acc[i][j][0]), "+f"(acc[i][j][1]),
                          "+f"(acc[i][j][2]), "+f"(acc[i][j][3])
                        : "r"(af[i].x), "r"(af[i].y), "r"(af[i].z), "r"(af[i].w),
                          "r"(bf[j].x), "r"(bf[j].y));
        }

        if (c + 1 < NCH) STORE_CHUNK((c + 1) & 1);
        __syncthreads();
    }

    // Epilogue: c0,c1 -> row = groupID; c2,c3 -> row+8; cols = 2*tig + {0,1}
    const int grp = lane >> 2, tig = lane & 3;
#pragma unroll
    for (int i = 0; i < 4; i++) {
        int r = row0 + wm * 64 + i * 16 + grp;
#pragma unroll
        for (int j = 0; j < 4; j++) {
            int cc = col0 + wn * 32 + j * 8 + (tig << 1);
            *(float2*)(C + (size_t)r * CDIM + cc) =
                make_float2(acc[i][j][0], acc[i][j][1]);
            *(float2*)(C + (size_t)(r + 8) * CDIM + cc) =
                make_float2(acc[i][j][2], acc[i][j][3]);
        }
    }
#undef STORE_CHUNK
}

// ---------------------------------------------------------------------------
// Flash attention, fp32 (unchanged, known-correct). One block = 64 queries.
// K tile == Q tile data (reference bug: K uses W_q). Causal.
// ---------------------------------------------------------------------------
#define QPAD 68
#define PPAD 65
#define ATT_SMEM ((3 * 64 * QPAD + 64 * PPAD) * 4)  // 68864 bytes

__global__ __launch_bounds__(256) void attn_kernel(
    const float* __restrict__ Q, const float* __restrict__ V,
    float* __restrict__ O)
{
    extern __shared__ float sm[];
    float* Qs = sm;                 // [64][QPAD] : [d][i]
    float* Ks = Qs + 64 * QPAD;     // [64][QPAD] : [d][j]
    float* Vs = Ks + 64 * QPAD;     // [64][QPAD] : [j][d]
    float* Ps = Vs + 64 * QPAD;     // [64][PPAD] : [j][i]

    const int tid = threadIdx.x;
    const int tx = tid & 15;
    const int ty = tid >> 4;
    const int qb = blockIdx.x;
    const int bh = blockIdx.y;
    const int b = bh >> 4, h = bh & 15;
    const int t0 = qb * 64;

    const float* Qbase = Q + (size_t)b * TSEQ * CDIM + h * DH;
    const float* Vbase = V + (size_t)b * TSEQ * CDIM + h * DH;

#pragma unroll
    for (int p = 0; p < 4; p++) {
        int i = p * 16 + ty;
        int d = tx << 2;
        float4 q4 = *(const float4*)(Qbase + (size_t)(t0 + i) * CDIM + d);
        Qs[(d + 0) * QPAD + i] = q4.x;
        Qs[(d + 1) * QPAD + i] = q4.y;
        Qs[(d + 2) * QPAD + i] = q4.z;
        Qs[(d + 3) * QPAD + i] = q4.w;
    }

    float m[4], l[4], o[4][4];
#pragma unroll
    for (int i = 0; i < 4; i++) {
        m[i] = -1e30f; l[i] = 0.f;
#pragma unroll
        for (int j = 0; j < 4; j++) o[i][j] = 0.f;
    }

    const float scale = 0.125f;

    for (int jt = 0; jt <= qb; jt++) {
        const int j0 = jt * 64;
        __syncthreads();
#pragma unroll
        for (int p = 0; p < 4; p++) {
            int j = p * 16 + ty;
            int d = tx << 2;
            float4 k4 = *(const float4*)(Qbase + (size_t)(j0 + j) * CDIM + d);
            Ks[(d + 0) * QPAD + j] = k4.x;
            Ks[(d + 1) * QPAD + j] = k4.y;
            Ks[(d + 2) * QPAD + j] = k4.z;
            Ks[(d + 3) * QPAD + j] = k4.w;
            float4 v4 = *(const float4*)(Vbase + (size_t)(j0 + j) * CDIM + d);
            *(float4*)(Vs + j * QPAD + d) = v4;
        }
        __syncthreads();

        float s[4][4];
#pragma unroll
        for (int i = 0; i < 4; i++)
#pragma unroll
            for (int j = 0; j < 4; j++) s[i][j] = 0.f;
#pragma unroll 8
        for (int d = 0; d < 64; d++) {
            float4 av = *(const float4*)(Qs + d * QPAD + (ty << 2));
            float4 bv = *(const float4*)(Ks + d * QPAD + (tx << 2));
            float a[4] = {av.x, av.y, av.z, av.w};
            float bb[4] = {bv.x, bv.y, bv.z, bv.w};
#pragma unroll
            for (int i = 0; i < 4; i++)
#pragma unroll
                for (int j = 0; j < 4; j++)
                    s[i][j] = fmaf(a[i], bb[j], s[i][j]);
        }

        if (jt == qb) {
#pragma unroll
            for (int ii = 0; ii < 4; ii++)
#pragma unroll
                for (int jj = 0; jj < 4; jj++)
                    if ((tx << 2) + jj > (ty << 2) + ii) s[ii][jj] = -1e38f;
        }

#pragma unroll
        for (int ii = 0; ii < 4; ii++) {
            float mx = -1e30f;
#pragma unroll
            for (int jj = 0; jj < 4; jj++) {
                s[ii][jj] = (s[ii][jj] <= -1e37f) ? -1e30f : s[ii][jj] * scale;
                mx = fmaxf(mx, s[ii][jj]);
            }
#pragma unroll
            for (int off = 8; off >= 1; off >>= 1)
                mx = fmaxf(mx, __shfl_xor_sync(0xffffffffu, mx, off));
            float mnew = fmaxf(m[ii], mx);
            float alpha = __expf(m[ii] - mnew);
            m[ii] = mnew;
            float p[4], psum = 0.f;
#pragma unroll
            for (int jj = 0; jj < 4; jj++) {
                p[jj] = __expf(s[ii][jj] - mnew);
                psum += p[jj];
            }
#pragma unroll
            for (int off = 8; off >= 1; off >>= 1)
                psum += __shfl_xor_sync(0xffffffffu, psum, off);
            l[ii] = l[ii] * alpha + psum;
#pragma unroll
            for (int jj = 0; jj < 4; jj++) o[ii][jj] *= alpha;
#pragma unroll
            for (int jj = 0; jj < 4; jj++)
                Ps[((tx << 2) + jj) * PPAD + (ty << 2) + ii] = p[jj];
        }
        __syncthreads();

#pragma unroll 8
        for (int j = 0; j < 64; j++) {
            float a[4];
#pragma unroll
            for (int ii = 0; ii < 4; ii++)
                a[ii] = Ps[j * PPAD + (ty << 2) + ii];
            float4 bv = *(const float4*)(Vs + j * QPAD + (tx << 2));
            float bb[4] = {bv.x, bv.y, bv.z, bv.w};
#pragma unroll
            for (int ii = 0; ii < 4; ii++)
#pragma unroll
                for (int jj = 0; jj < 4; jj++)
                    o[ii][jj] = fmaf(a[ii], bb[jj], o[ii][jj]);
        }
    }

    float* Obase = O + (size_t)b * TSEQ * CDIM + h * DH;
#pragma unroll
    for (int ii = 0; ii < 4; ii++) {
        float inv = 1.0f / l[ii];
        float4 o4 = make_float4(o[ii][0] * inv, o[ii][1] * inv,
                                o[ii][2] * inv, o[ii][3] * inv);
        *(float4*)(Obase + (size_t)(t0 + (ty << 2) + ii) * CDIM + (tx << 2)) = o4;
    }
}

// ---------------------------------------------------------------------------
extern "C" void kernel_launch(void* const* d_in, const int* in_sizes, int n_in,
                              void* d_out, int out_size)
{
    (void)in_sizes; (void)n_in; (void)out_size;
    const float* x  = (const float*)d_in[0];
    const float* Wq = (const float*)d_in[1];
    // d_in[2] (W_k) intentionally unused: reference computes K with W_q
    const float* Wv = (const float*)d_in[3];
    const float* Wo = (const float*)d_in[4];
    float* out = (float*)d_out;

    float *Qb, *Vb, *Ob;
    cudaGetSymbolAddress((void**)&Qb, g_Q);
    cudaGetSymbolAddress((void**)&Vb, g_V);
    cudaGetSymbolAddress((void**)&Ob, g_O);

    cudaFuncSetAttribute(gemm_mma, cudaFuncAttributeMaxDynamicSharedMemorySize,
                         GEMM_SMEM);
    cudaFuncSetAttribute(attn_kernel, cudaFuncAttributeMaxDynamicSharedMemorySize,
                         ATT_SMEM);

    dim3 gg(CDIM / 128, MTOT / 128);  // (8, 64)
    gemm_mma<<<gg, 256, GEMM_SMEM>>>(x, Wq, Qb);
    gemm_mma<<<gg, 256, GEMM_SMEM>>>(x, Wv, Vb);

    attn_kernel<<<dim3(TSEQ / 64, 4 * NHEAD), 256, ATT_SMEM>>>(Qb, Vb, Ob);

    gemm_mma<<<gg, 256, GEMM_SMEM>>>(Ob, Wo, out);
}

// round 7
// speedup vs baseline: 2.0638x; 1.3888x over previous
#include <cuda_runtime.h>
#include <math.h>
#include <stdint.h>

#define MTOT 8192
#define CDIM 1024
#define NHEAD 16
#define DH 64
#define TSEQ 2048

// Scratch (allocation-free rule: __device__ globals)
__device__ float g_Q[(size_t)MTOT * CDIM];
__device__ float g_V[(size_t)MTOT * CDIM];
__device__ float g_O[(size_t)MTOT * CDIM];

__device__ __forceinline__ float f2tf32f(float v) {
    uint32_t r;
    asm("cvt.rna.tf32.f32 %0, %1;" : "=r"(r) : "f"(v));
    return __uint_as_float(r);
}
__device__ __forceinline__ uint32_t f2tf32u(float v) {
    uint32_t r;
    asm("cvt.rna.tf32.f32 %0, %1;" : "=r"(r) : "f"(v));
    return r;
}

#define MMA_TF32(acc, a, b)                                                    \
    asm volatile(                                                              \
        "mma.sync.aligned.m16n8k8.row.col.f32.tf32.tf32.f32 "                  \
        "{%0,%1,%2,%3}, {%4,%5,%6,%7}, {%8,%9}, {%0,%1,%2,%3};"                \
        : "+f"((acc)[0]), "+f"((acc)[1]), "+f"((acc)[2]), "+f"((acc)[3])       \
        : "r"((a)[0]), "r"((a)[1]), "r"((a)[2]), "r"((a)[3]),                  \
          "r"((b).x), "r"((b).y))

// ===========================================================================
// tf32 mma.sync GEMM:  C[M,N] = A[M,K] @ B[N,K]^T   (unchanged from R5 WIN)
// ===========================================================================
#define NCH (CDIM / 32)          // 32 chunks
#define GEMM_SMEM (4 * 4096 * 4) // 64 KB

__global__ __launch_bounds__(256) void gemm_mma(
    const float* __restrict__ A, const float* __restrict__ B,
    float* __restrict__ C)
{
    extern __shared__ float smem[];
    const int tid = threadIdx.x;
    const int lane = tid & 31;
    const int wid = tid >> 5;
    const int wm = wid & 1;
    const int wn = wid >> 1;
    const int row0 = blockIdx.y * 128;
    const int col0 = blockIdx.x * 128;

    float acc[4][4][4];
#pragma unroll
    for (int i = 0; i < 4; i++)
#pragma unroll
        for (int j = 0; j < 4; j++)
#pragma unroll
            for (int r = 0; r < 4; r++) acc[i][j][r] = 0.f;

    const int lrow = tid >> 3;
    const int lk   = (tid & 7) << 2;
    const int ksA  = lk >> 3;
    const int regHi = (lk >> 2) & 1;

    const float* Ab = A + (size_t)(row0 + lrow) * CDIM + lk;
    const float* Bb = B + (size_t)(col0 + lrow) * CDIM + lk;

    float4 ra[4], rb[4];

#define STORE_CHUNK(buf) do {                                                  \
    float* Abuf = smem + (buf) * 4096;                                         \
    float* Bbuf = smem + 8192 + (buf) * 4096;                                  \
    _Pragma("unroll")                                                          \
    for (int i = 0; i < 4; i++) {                                              \
        int r = i * 32 + lrow;                                                 \
        int mt = r >> 4, rm = r & 15;                                          \
        float* da = &Abuf[(((mt * 4 + ksA) * 32) + ((rm & 7) << 2)) * 4        \
                          + ((rm >> 3) | (regHi << 1))];                       \
        da[0]  = f2tf32f(ra[i].x); da[4]  = f2tf32f(ra[i].y);                  \
        da[8]  = f2tf32f(ra[i].z); da[12] = f2tf32f(ra[i].w);                  \
        int nt = r >> 3, nn = r & 7;                                           \
        float* db = &Bbuf[(((nt * 4 + ksA) * 32) + (nn << 2)) * 2 + regHi];    \
        db[0] = f2tf32f(rb[i].x); db[2] = f2tf32f(rb[i].y);                    \
        db[4] = f2tf32f(rb[i].z); db[6] = f2tf32f(rb[i].w);                    \
    }                                                                          \
} while (0)

#pragma unroll
    for (int i = 0; i < 4; i++) {
        ra[i] = *(const float4*)(Ab + (size_t)(i * 32) * CDIM);
        rb[i] = *(const float4*)(Bb + (size_t)(i * 32) * CDIM);
    }
    STORE_CHUNK(0);
    __syncthreads();

    for (int c = 0; c < NCH; c++) {
        const int cur = c & 1;
        if (c + 1 < NCH) {
#pragma unroll
            for (int i = 0; i < 4; i++) {
                ra[i] = *(const float4*)(Ab + (size_t)(i * 32) * CDIM + (c + 1) * 32);
                rb[i] = *(const float4*)(Bb + (size_t)(i * 32) * CDIM + (c + 1) * 32);
            }
        }

        const float* Abuf = smem + cur * 4096;
        const float* Bbuf = smem + 8192 + cur * 4096;
#pragma unroll
        for (int ks = 0; ks < 4; ks++) {
            uint4 af[4]; uint2 bf[4];
#pragma unroll
            for (int i = 0; i < 4; i++)
                af[i] = *(const uint4*)&Abuf[(((wm * 4 + i) * 4 + ks) * 32 + lane) * 4];
#pragma unroll
            for (int j = 0; j < 4; j++)
                bf[j] = *(const uint2*)&Bbuf[(((wn * 4 + j) * 4 + ks) * 32 + lane) * 2];
#pragma unroll
            for (int i = 0; i < 4; i++)
#pragma unroll
                for (int j = 0; j < 4; j++)
                    asm volatile(
                        "mma.sync.aligned.m16n8k8.row.col.f32.tf32.tf32.f32 "
                        "{%0,%1,%2,%3}, {%4,%5,%6,%7}, {%8,%9}, {%0,%1,%2,%3};"
                        : "+f"(acc[i][j][0]), "+f"(acc[i][j][1]),
                          "+f"(acc[i][j][2]), "+f"(acc[i][j][3])
                        : "r"(af[i].x), "r"(af[i].y), "r"(af[i].z), "r"(af[i].w),
                          "r"(bf[j].x), "r"(bf[j].y));
        }

        if (c + 1 < NCH) STORE_CHUNK((c + 1) & 1);
        __syncthreads();
    }

    const int grp = lane >> 2, tig = lane & 3;
#pragma unroll
    for (int i = 0; i < 4; i++) {
        int r = row0 + wm * 64 + i * 16 + grp;
#pragma unroll
        for (int j = 0; j < 4; j++) {
            int cc = col0 + wn * 32 + j * 8 + (tig << 1);
            *(float2*)(C + (size_t)r * CDIM + cc) =
                make_float2(acc[i][j][0], acc[i][j][1]);
            *(float2*)(C + (size_t)(r + 8) * CDIM + cc) =
                make_float2(acc[i][j][2], acc[i][j][3]);
        }
    }
#undef STORE_CHUNK
}

// ===========================================================================
// Tensorized flash attention (tf32 mma.sync). CTA = 64 queries, 4 warps
// (16 rows each), 64-key tiles, Dh=64. K tile == Q tile data (ref bug).
// K/V stored in smem PRE-PERMUTED into m16n8k8 B-fragment order; Q held
// in A-fragments in registers; P round-trips a 68-padded smem tile.
// Smem: Kbuf 4096f | Vbuf 4096f | Pbuf/Qstage 64*68f  = 50176 bytes.
// ===========================================================================
#define KBUF 0
#define VBUF 4096
#define PBUF 8192
#define ATT_SMEM ((8192 + 64 * 68) * 4)

__global__ __launch_bounds__(128) void attn_mma(
    const float* __restrict__ Q, const float* __restrict__ V,
    float* __restrict__ O)
{
    extern __shared__ float sm[];
    const int tid = threadIdx.x;
    const int lane = tid & 31, w = tid >> 5;
    const int grp = lane >> 2, tig = lane & 3;
    const int qb = blockIdx.x;          // 0..31
    const int bh = blockIdx.y;          // 0..63
    const int b = bh >> 4, h = bh & 15;
    const int t0 = qb * 64;

    const float* Qbase = Q + (size_t)b * TSEQ * CDIM + h * DH;
    const float* Vbase = V + (size_t)b * TSEQ * CDIM + h * DH;

    // ---- Stage Q tile plain into Pbuf, then pick up A-fragments ----
#pragma unroll
    for (int i = 0; i < 8; i++) {
        int idx = i * 128 + tid;
        int r = idx >> 4, c = (idx & 15) << 2;
        float4 q4 = *(const float4*)(Qbase + (size_t)(t0 + r) * CDIM + c);
        float* dst = &sm[PBUF + r * 68 + c];
        dst[0] = q4.x; dst[1] = q4.y; dst[2] = q4.z; dst[3] = q4.w;
    }
    __syncthreads();
    uint32_t qa[8][4];
    {
        const float* Qs = &sm[PBUF + (w * 16) * 68];
#pragma unroll
        for (int ks = 0; ks < 8; ks++) {
            qa[ks][0] = f2tf32u(Qs[grp * 68 + ks * 8 + tig]);
            qa[ks][1] = f2tf32u(Qs[(grp + 8) * 68 + ks * 8 + tig]);
            qa[ks][2] = f2tf32u(Qs[grp * 68 + ks * 8 + tig + 4]);
            qa[ks][3] = f2tf32u(Qs[(grp + 8) * 68 + ks * 8 + tig + 4]);
        }
    }
    __syncthreads();   // Pbuf gets reused for P

    float oacc[8][4];
#pragma unroll
    for (int nt = 0; nt < 8; nt++)
#pragma unroll
        for (int r = 0; r < 4; r++) oacc[nt][r] = 0.f;
    float m0 = -1e30f, m1 = -1e30f, l0 = 0.f, l1 = 0.f;

    const int row0g = t0 + w * 16 + grp;
    const int row1g = row0g + 8;
    const float scale = 0.125f;   // 1/sqrt(64)

    for (int jt = 0; jt <= qb; jt++) {
        const int j0 = jt * 64;

        // ---- Load K,V tiles into B-fragment-ordered smem ----
#pragma unroll
        for (int i = 0; i < 8; i++) {
            int idx = i * 128 + tid;
            int r = idx >> 4, c = (idx & 15) << 2;   // r=row(key), c=dh base
            float4 k4 = *(const float4*)(Qbase + (size_t)(j0 + r) * CDIM + c);
            float4 v4 = *(const float4*)(Vbase + (size_t)(j0 + r) * CDIM + c);
            // K: B-frag with n=key(r), k=dh(c+d)
            float* kb = &sm[KBUF + (((r >> 3) * 8 + (c >> 3)) * 32
                                    + ((r & 7) << 2)) * 2 + ((c >> 2) & 1)];
            kb[0] = f2tf32f(k4.x); kb[2] = f2tf32f(k4.y);
            kb[4] = f2tf32f(k4.z); kb[6] = f2tf32f(k4.w);
            // V: B-frag with n=dh(c+d), k=key(r)
            float* vb = &sm[VBUF + (((c >> 3) * 8 + (r >> 3)) * 32
                                    + ((c & 7) << 2) + (r & 3)) * 2 + ((r >> 2) & 1)];
            vb[0] = f2tf32f(v4.x); vb[8]  = f2tf32f(v4.y);
            vb[16] = f2tf32f(v4.z); vb[24] = f2tf32f(v4.w);
        }
        __syncthreads();

        // ---- S = Q K^T ----
        float sc[8][4];
#pragma unroll
        for (int nt = 0; nt < 8; nt++) {
            sc[nt][0] = 0.f; sc[nt][1] = 0.f; sc[nt][2] = 0.f; sc[nt][3] = 0.f;
#pragma unroll
            for (int ks = 0; ks < 8; ks++) {
                uint2 kb = *(const uint2*)&sm[KBUF + ((nt * 8 + ks) * 32 + lane) * 2];
                MMA_TF32(sc[nt], qa[ks], kb);
            }
        }

        // ---- scale + causal mask ----
#pragma unroll
        for (int nt = 0; nt < 8; nt++) {
            sc[nt][0] *= scale; sc[nt][1] *= scale;
            sc[nt][2] *= scale; sc[nt][3] *= scale;
        }
        if (jt == qb) {
#pragma unroll
            for (int nt = 0; nt < 8; nt++) {
                int c = j0 + nt * 8 + (tig << 1);
                if (c > row0g)     sc[nt][0] = -1e30f;
                if (c + 1 > row0g) sc[nt][1] = -1e30f;
                if (c > row1g)     sc[nt][2] = -1e30f;
                if (c + 1 > row1g) sc[nt][3] = -1e30f;
            }
        }

        // ---- online softmax (rows live in lane quads) ----
        float mx0 = -1e30f, mx1 = -1e30f;
#pragma unroll
        for (int nt = 0; nt < 8; nt++) {
            mx0 = fmaxf(mx0, fmaxf(sc[nt][0], sc[nt][1]));
            mx1 = fmaxf(mx1, fmaxf(sc[nt][2], sc[nt][3]));
        }
        mx0 = fmaxf(mx0, __shfl_xor_sync(0xffffffffu, mx0, 1));
        mx0 = fmaxf(mx0, __shfl_xor_sync(0xffffffffu, mx0, 2));
        mx1 = fmaxf(mx1, __shfl_xor_sync(0xffffffffu, mx1, 1));
        mx1 = fmaxf(mx1, __shfl_xor_sync(0xffffffffu, mx1, 2));

        float mn0 = fmaxf(m0, mx0), mn1 = fmaxf(m1, mx1);
        float al0 = __expf(m0 - mn0), al1 = __expf(m1 - mn1);
        m0 = mn0; m1 = mn1;

        float ps0 = 0.f, ps1 = 0.f;
        float* Pr = &sm[PBUF + (w * 16) * 68];
#pragma unroll
        for (int nt = 0; nt < 8; nt++) {
            float p0 = __expf(sc[nt][0] - mn0);
            float p1 = __expf(sc[nt][1] - mn0);
            float p2 = __expf(sc[nt][2] - mn1);
            float p3 = __expf(sc[nt][3] - mn1);
            ps0 += p0 + p1; ps1 += p2 + p3;
            *(float2*)&Pr[grp * 68 + nt * 8 + (tig << 1)] =
                make_float2(f2tf32f(p0), f2tf32f(p1));
            *(float2*)&Pr[(grp + 8) * 68 + nt * 8 + (tig << 1)] =
                make_float2(f2tf32f(p2), f2tf32f(p3));
        }
        ps0 += __shfl_xor_sync(0xffffffffu, ps0, 1);
        ps0 += __shfl_xor_sync(0xffffffffu, ps0, 2);
        ps1 += __shfl_xor_sync(0xffffffffu, ps1, 1);
        ps1 += __shfl_xor_sync(0xffffffffu, ps1, 2);
        l0 = l0 * al0 + ps0;
        l1 = l1 * al1 + ps1;

#pragma unroll
        for (int nt = 0; nt < 8; nt++) {
            oacc[nt][0] *= al0; oacc[nt][1] *= al0;
            oacc[nt][2] *= al1; oacc[nt][3] *= al1;
        }
        __syncwarp();

        // ---- O += P V ----
#pragma unroll
        for (int ks = 0; ks < 8; ks++) {
            uint32_t pa[4];
            pa[0] = __float_as_uint(Pr[grp * 68 + ks * 8 + tig]);
            pa[1] = __float_as_uint(Pr[(grp + 8) * 68 + ks * 8 + tig]);
            pa[2] = __float_as_uint(Pr[grp * 68 + ks * 8 + tig + 4]);
            pa[3] = __float_as_uint(Pr[(grp + 8) * 68 + ks * 8 + tig + 4]);
#pragma unroll
            for (int nt = 0; nt < 8; nt++) {
                uint2 vb = *(const uint2*)&sm[VBUF + ((nt * 8 + ks) * 32 + lane) * 2];
                MMA_TF32(oacc[nt], pa, vb);
            }
        }
        __syncthreads();   // all warps done with K/V before next overwrite
    }

    // ---- epilogue ----
    float inv0 = 1.f / l0, inv1 = 1.f / l1;
    float* Ob = O + (size_t)b * TSEQ * CDIM + h * DH;
#pragma unroll
    for (int nt = 0; nt < 8; nt++) {
        int cc = nt * 8 + (tig << 1);
        *(float2*)(Ob + (size_t)row0g * CDIM + cc) =
            make_float2(oacc[nt][0] * inv0, oacc[nt][1] * inv0);
        *(float2*)(Ob + (size_t)row1g * CDIM + cc) =
            make_float2(oacc[nt][2] * inv1, oacc[nt][3] * inv1);
    }
}

// ---------------------------------------------------------------------------
extern "C" void kernel_launch(void* const* d_in, const int* in_sizes, int n_in,
                              void* d_out, int out_size)
{
    (void)in_sizes; (void)n_in; (void)out_size;
    const float* x  = (const float*)d_in[0];
    const float* Wq = (const float*)d_in[1];
    // d_in[2] (W_k) intentionally unused: reference computes K with W_q
    const float* Wv = (const float*)d_in[3];
    const float* Wo = (const float*)d_in[4];
    float* out = (float*)d_out;

    float *Qb, *Vb, *Ob;
    cudaGetSymbolAddress((void**)&Qb, g_Q);
    cudaGetSymbolAddress((void**)&Vb, g_V);
    cudaGetSymbolAddress((void**)&Ob, g_O);

    cudaFuncSetAttribute(gemm_mma, cudaFuncAttributeMaxDynamicSharedMemorySize,
                         GEMM_SMEM);
    cudaFuncSetAttribute(attn_mma, cudaFuncAttributeMaxDynamicSharedMemorySize,
                         ATT_SMEM);

    dim3 gg(CDIM / 128, MTOT / 128);  // (8, 64)
    gemm_mma<<<gg, 256, GEMM_SMEM>>>(x, Wq, Qb);
    gemm_mma<<<gg, 256, GEMM_SMEM>>>(x, Wv, Vb);

    attn_mma<<<dim3(TSEQ / 64, 4 * NHEAD), 128, ATT_SMEM>>>(Qb, Vb, Ob);

    gemm_mma<<<gg, 256, GEMM_SMEM>>>(Ob, Wo, out);
}

// round 11
// speedup vs baseline: 2.3898x; 1.1580x over previous
#include <cuda_runtime.h>
#include <math.h>
#include <stdint.h>

#define MTOT 8192
#define CDIM 1024
#define NHEAD 16
#define DH 64
#define TSEQ 2048

// Scratch (allocation-free rule: __device__ globals)
__device__ float g_Q[(size_t)MTOT * CDIM];
__device__ float g_V[(size_t)MTOT * CDIM];
__device__ float g_O[(size_t)MTOT * CDIM];

__device__ __forceinline__ float f2tf32f(float v) {
    uint32_t r;
    asm("cvt.rna.tf32.f32 %0, %1;" : "=r"(r) : "f"(v));
    return __uint_as_float(r);
}
__device__ __forceinline__ uint32_t f2tf32u(float v) {
    uint32_t r;
    asm("cvt.rna.tf32.f32 %0, %1;" : "=r"(r) : "f"(v));
    return r;
}

#define MMA_TF32(acc, a, b)                                                    \
    asm volatile(                                                              \
        "mma.sync.aligned.m16n8k8.row.col.f32.tf32.tf32.f32 "                  \
        "{%0,%1,%2,%3}, {%4,%5,%6,%7}, {%8,%9}, {%0,%1,%2,%3};"                \
        : "+f"((acc)[0]), "+f"((acc)[1]), "+f"((acc)[2]), "+f"((acc)[3])       \
        : "r"((a)[0]), "r"((a)[1]), "r"((a)[2]), "r"((a)[3]),                  \
          "r"((b).x), "r"((b).y))

// ===========================================================================
// tf32 mma.sync GEMM:  C[M,N] = A[M,K] @ B[N,K]^T   (unchanged from R5 WIN)
// ===========================================================================
#define NCH (CDIM / 32)          // 32 chunks
#define GEMM_SMEM (4 * 4096 * 4) // 64 KB

__global__ __launch_bounds__(256) void gemm_mma(
    const float* __restrict__ A, const float* __restrict__ B,
    float* __restrict__ C)
{
    extern __shared__ float smem[];
    const int tid = threadIdx.x;
    const int lane = tid & 31;
    const int wid = tid >> 5;
    const int wm = wid & 1;
    const int wn = wid >> 1;
    const int row0 = blockIdx.y * 128;
    const int col0 = blockIdx.x * 128;

    float acc[4][4][4];
#pragma unroll
    for (int i = 0; i < 4; i++)
#pragma unroll
        for (int j = 0; j < 4; j++)
#pragma unroll
            for (int r = 0; r < 4; r++) acc[i][j][r] = 0.f;

    const int lrow = tid >> 3;
    const int lk   = (tid & 7) << 2;
    const int ksA  = lk >> 3;
    const int regHi = (lk >> 2) & 1;

    const float* Ab = A + (size_t)(row0 + lrow) * CDIM + lk;
    const float* Bb = B + (size_t)(col0 + lrow) * CDIM + lk;

    float4 ra[4], rb[4];

#define STORE_CHUNK(buf) do {                                                  \
    float* Abuf = smem + (buf) * 4096;                                         \
    float* Bbuf = smem + 8192 + (buf) * 4096;                                  \
    _Pragma("unroll")                                                          \
    for (int i = 0; i < 4; i++) {                                              \
        int r = i * 32 + lrow;                                                 \
        int mt = r >> 4, rm = r & 15;                                          \
        float* da = &Abuf[(((mt * 4 + ksA) * 32) + ((rm & 7) << 2)) * 4        \
                          + ((rm >> 3) | (regHi << 1))];                       \
        da[0]  = f2tf32f(ra[i].x); da[4]  = f2tf32f(ra[i].y);                  \
        da[8]  = f2tf32f(ra[i].z); da[12] = f2tf32f(ra[i].w);                  \
        int nt = r >> 3, nn = r & 7;                                           \
        float* db = &Bbuf[(((nt * 4 + ksA) * 32) + (nn << 2)) * 2 + regHi];    \
        db[0] = f2tf32f(rb[i].x); db[2] = f2tf32f(rb[i].y);                    \
        db[4] = f2tf32f(rb[i].z); db[6] = f2tf32f(rb[i].w);                    \
    }                                                                          \
} while (0)

#pragma unroll
    for (int i = 0; i < 4; i++) {
        ra[i] = *(const float4*)(Ab + (size_t)(i * 32) * CDIM);
        rb[i] = *(const float4*)(Bb + (size_t)(i * 32) * CDIM);
    }
    STORE_CHUNK(0);
    __syncthreads();

    for (int c = 0; c < NCH; c++) {
        const int cur = c & 1;
        if (c + 1 < NCH) {
#pragma unroll
            for (int i = 0; i < 4; i++) {
                ra[i] = *(const float4*)(Ab + (size_t)(i * 32) * CDIM + (c + 1) * 32);
                rb[i] = *(const float4*)(Bb + (size_t)(i * 32) * CDIM + (c + 1) * 32);
            }
        }

        const float* Abuf = smem + cur * 4096;
        const float* Bbuf = smem + 8192 + cur * 4096;
#pragma unroll
        for (int ks = 0; ks < 4; ks++) {
            uint4 af[4]; uint2 bf[4];
#pragma unroll
            for (int i = 0; i < 4; i++)
                af[i] = *(const uint4*)&Abuf[(((wm * 4 + i) * 4 + ks) * 32 + lane) * 4];
#pragma unroll
            for (int j = 0; j < 4; j++)
                bf[j] = *(const uint2*)&Bbuf[(((wn * 4 + j) * 4 + ks) * 32 + lane) * 2];
#pragma unroll
            for (int i = 0; i < 4; i++)
#pragma unroll
                for (int j = 0; j < 4; j++)
                    asm volatile(
                        "mma.sync.aligned.m16n8k8.row.col.f32.tf32.tf32.f32 "
                        "{%0,%1,%2,%3}, {%4,%5,%6,%7}, {%8,%9}, {%0,%1,%2,%3};"
                        : "+f"(acc[i][j][0]), "+f"(acc[i][j][1]),
                          "+f"(acc[i][j][2]), "+f"(acc[i][j][3])
                        : "r"(af[i].x), "r"(af[i].y), "r"(af[i].z), "r"(af[i].w),
                          "r"(bf[j].x), "r"(bf[j].y));
        }

        if (c + 1 < NCH) STORE_CHUNK((c + 1) & 1);
        __syncthreads();
    }

    const int grp = lane >> 2, tig = lane & 3;
#pragma unroll
    for (int i = 0; i < 4; i++) {
        int r = row0 + wm * 64 + i * 16 + grp;
#pragma unroll
        for (int j = 0; j < 4; j++) {
            int cc = col0 + wn * 32 + j * 8 + (tig << 1);
            *(float2*)(C + (size_t)r * CDIM + cc) =
                make_float2(acc[i][j][0], acc[i][j][1]);
            *(float2*)(C + (size_t)(r + 8) * CDIM + cc) =
                make_float2(acc[i][j][2], acc[i][j][3]);
        }
    }
#undef STORE_CHUNK
}

// ===========================================================================
// Tensorized flash attention v2 (tf32 mma.sync).
// CTA = 128 queries, 8 warps (16 rows each), 64-key tiles, Dh=64.
// K tile == Q tile data (ref bug: K uses W_q). Causal.
//  - Q A-fragments loaded directly from global (no staging).
//  - K/V double-buffered in smem, pre-permuted into B-fragment order.
//  - P never touches smem: S-frag -> A-frag via width-4 shfl permutation.
//  - 1 __syncthreads per key tile; next tile prefetched right after barrier.
//  - Warps fully below the diagonal tile skip compute.
// Smem: 2 buffers x (K 4096f + V 4096f) = 64 KB.
// ===========================================================================
#define ATT_SMEM (2 * 8192 * 4)

__global__ __launch_bounds__(256, 2) void attn_mma(
    const float* __restrict__ Q, const float* __restrict__ V,
    float* __restrict__ O)
{
    extern __shared__ float sm[];
    const int tid = threadIdx.x;
    const int lane = tid & 31, w = tid >> 5;
    const int grp = lane >> 2, tig = lane & 3;
    const int qb = (int)gridDim.x - 1 - (int)blockIdx.x;  // longest first
    const int bh = blockIdx.y;
    const int b = bh >> 4, h = bh & 15;
    const int t0 = qb * 128;

    const float* Qbase = Q + (size_t)b * TSEQ * CDIM + h * DH;
    const float* Vbase = V + (size_t)b * TSEQ * CDIM + h * DH;

    const int row0g = t0 + w * 16 + grp;   // global row of acc half 0
    const int row1g = row0g + 8;
    const int wrow_max = t0 + w * 16 + 15;

    // ---- Q A-fragments straight from global ----
    uint32_t qa[8][4];
    {
        const float* q0 = Qbase + (size_t)row0g * CDIM;
        const float* q1 = Qbase + (size_t)row1g * CDIM;
#pragma unroll
        for (int ks = 0; ks < 8; ks++) {
            qa[ks][0] = f2tf32u(q0[ks * 8 + tig]);
            qa[ks][1] = f2tf32u(q1[ks * 8 + tig]);
            qa[ks][2] = f2tf32u(q0[ks * 8 + tig + 4]);
            qa[ks][3] = f2tf32u(q1[ks * 8 + tig + 4]);
        }
    }

    float oacc[8][4];
#pragma unroll
    for (int nt = 0; nt < 8; nt++)
#pragma unroll
        for (int r = 0; r < 4; r++) oacc[nt][r] = 0.f;
    float m0 = -1e30f, m1 = -1e30f, l0 = 0.f, l1 = 0.f;

    const float scale = 0.125f;   // 1/sqrt(64)
    const int ntiles = 2 * qb + 2;

    // ---- cooperative K/V tile load into fragment-ordered smem buffer ----
#define LOAD_KV(j0, buf) do {                                                  \
    float* Kb_ = &sm[(buf) * 8192];                                            \
    float* Vb_ = Kb_ + 4096;                                                   \
    _Pragma("unroll")                                                          \
    for (int i = 0; i < 4; i++) {                                              \
        int idx = i * 256 + tid;                                               \
        int r = idx >> 4, c = (idx & 15) << 2;                                 \
        float4 k4 = *(const float4*)(Qbase + (size_t)((j0) + r) * CDIM + c);   \
        float4 v4 = *(const float4*)(Vbase + (size_t)((j0) + r) * CDIM + c);   \
        float* kb = &Kb_[(((r >> 3) * 8 + (c >> 3)) * 32                       \
                          + ((r & 7) << 2)) * 2 + ((c >> 2) & 1)];             \
        kb[0] = f2tf32f(k4.x); kb[2] = f2tf32f(k4.y);                          \
        kb[4] = f2tf32f(k4.z); kb[6] = f2tf32f(k4.w);                          \
        float* vb = &Vb_[(((c >> 3) * 8 + (r >> 3)) * 32                       \
                          + ((c & 7) << 2) + (r & 3)) * 2 + ((r >> 2) & 1)];   \
        vb[0]  = f2tf32f(v4.x); vb[8]  = f2tf32f(v4.y);                        \
        vb[16] = f2tf32f(v4.z); vb[24] = f2tf32f(v4.w);                        \
    }                                                                          \
} while (0)

    LOAD_KV(0, 0);

    for (int jt = 0; jt < ntiles; jt++) {
        const int j0 = jt * 64;
        __syncthreads();                 // tile jt visible; prev buf reusable
        if (jt + 1 < ntiles) LOAD_KV((jt + 1) * 64, (jt + 1) & 1);

        if (j0 <= wrow_max) {            // not fully masked for this warp
            const float* Kb = &sm[(jt & 1) * 8192];
            const float* Vb = Kb + 4096;

            // ---- S = Q K^T ----
            float sc[8][4];
#pragma unroll
            for (int nt = 0; nt < 8; nt++) {
                sc[nt][0] = 0.f; sc[nt][1] = 0.f; sc[nt][2] = 0.f; sc[nt][3] = 0.f;
#pragma unroll
                for (int ks = 0; ks < 8; ks++) {
                    uint2 kb = *(const uint2*)&Kb[((nt * 8 + ks) * 32 + lane) * 2];
                    MMA_TF32(sc[nt], qa[ks], kb);
                }
            }

            // ---- scale + causal mask (only when tile touches diagonal) ----
#pragma unroll
            for (int nt = 0; nt < 8; nt++) {
                sc[nt][0] *= scale; sc[nt][1] *= scale;
                sc[nt][2] *= scale; sc[nt][3] *= scale;
            }
            if (j0 + 63 > row0g) {
#pragma unroll
                for (int nt = 0; nt < 8; nt++) {
                    int c = j0 + nt * 8 + (tig << 1);
                    if (c > row0g)     sc[nt][0] = -1e30f;
                    if (c + 1 > row0g) sc[nt][1] = -1e30f;
                    if (c > row1g)     sc[nt][2] = -1e30f;
                    if (c + 1 > row1g) sc[nt][3] = -1e30f;
                }
            }

            // ---- online softmax (rows live in lane quads) ----
            float mx0 = -1e30f, mx1 = -1e30f;
#pragma unroll
            for (int nt = 0; nt < 8; nt++) {
                mx0 = fmaxf(mx0, fmaxf(sc[nt][0], sc[nt][1]));
                mx1 = fmaxf(mx1, fmaxf(sc[nt][2], sc[nt][3]));
            }
            mx0 = fmaxf(mx0, __shfl_xor_sync(0xffffffffu, mx0, 1));
            mx0 = fmaxf(mx0, __shfl_xor_sync(0xffffffffu, mx0, 2));
            mx1 = fmaxf(mx1, __shfl_xor_sync(0xffffffffu, mx1, 1));
            mx1 = fmaxf(mx1, __shfl_xor_sync(0xffffffffu, mx1, 2));

            float mn0 = fmaxf(m0, mx0), mn1 = fmaxf(m1, mx1);
            float al0 = __expf(m0 - mn0), al1 = __expf(m1 - mn1);
            m0 = mn0; m1 = mn1;

            float ps0 = 0.f, ps1 = 0.f;
#pragma unroll
            for (int nt = 0; nt < 8; nt++) {
                sc[nt][0] = __expf(sc[nt][0] - mn0);
                sc[nt][1] = __expf(sc[nt][1] - mn0);
                sc[nt][2] = __expf(sc[nt][2] - mn1);
                sc[nt][3] = __expf(sc[nt][3] - mn1);
                ps0 += sc[nt][0] + sc[nt][1];
                ps1 += sc[nt][2] + sc[nt][3];
            }
            ps0 += __shfl_xor_sync(0xffffffffu, ps0, 1);
            ps0 += __shfl_xor_sync(0xffffffffu, ps0, 2);
            ps1 += __shfl_xor_sync(0xffffffffu, ps1, 1);
            ps1 += __shfl_xor_sync(0xffffffffu, ps1, 2);
            l0 = l0 * al0 + ps0;
            l1 = l1 * al1 + ps1;

#pragma unroll
            for (int nt = 0; nt < 8; nt++) {
                oacc[nt][0] *= al0; oacc[nt][1] *= al0;
                oacc[nt][2] *= al1; oacc[nt][3] *= al1;
            }

            // ---- O += P V  (P via width-4 shuffle permutation) ----
            const int sL = tig >> 1;     // source lane-in-quad for k=tig
            const bool odd = tig & 1;
#pragma unroll
            for (int ks = 0; ks < 8; ks++) {
                float a0 = __shfl_sync(0xffffffffu, sc[ks][0], sL, 4);
                float a1 = __shfl_sync(0xffffffffu, sc[ks][1], sL, 4);
                float b0 = __shfl_sync(0xffffffffu, sc[ks][0], sL + 2, 4);
                float b1 = __shfl_sync(0xffffffffu, sc[ks][1], sL + 2, 4);
                float c0 = __shfl_sync(0xffffffffu, sc[ks][2], sL, 4);
                float c1 = __shfl_sync(0xffffffffu, sc[ks][3], sL, 4);
                float d0 = __shfl_sync(0xffffffffu, sc[ks][2], sL + 2, 4);
                float d1 = __shfl_sync(0xffffffffu, sc[ks][3], sL + 2, 4);
                uint32_t pa[4];
                pa[0] = f2tf32u(odd ? a1 : a0);   // (row0, k=tig)
                pa[1] = f2tf32u(odd ? c1 : c0);   // (row1, k=tig)
                pa[2] = f2tf32u(odd ? b1 : b0);   // (row0, k=tig+4)
                pa[3] = f2tf32u(odd ? d1 : d0);   // (row1, k=tig+4)
#pragma unroll
                for (int nt = 0; nt < 8; nt++) {
                    uint2 vb = *(const uint2*)&Vb[((nt * 8 + ks) * 32 + lane) * 2];
                    MMA_TF32(oacc[nt], pa, vb);
                }
            }
        }
    }
#undef LOAD_KV

    // ---- epilogue ----
    float inv0 = 1.f / l0, inv1 = 1.f / l1;
    float* Ob = O + (size_t)b * TSEQ * CDIM + h * DH;
#pragma unroll
    for (int nt = 0; nt < 8; nt++) {
        int cc = nt * 8 + (tig << 1);
        *(float2*)(Ob + (size_t)row0g * CDIM + cc) =
            make_float2(oacc[nt][0] * inv0, oacc[nt][1] * inv0);
        *(float2*)(Ob + (size_t)row1g * CDIM + cc) =
            make_float2(oacc[nt][2] * inv1, oacc[nt][3] * inv1);
    }
}

// ---------------------------------------------------------------------------
extern "C" void kernel_launch(void* const* d_in, const int* in_sizes, int n_in,
                              void* d_out, int out_size)
{
    (void)in_sizes; (void)n_in; (void)out_size;
    const float* x  = (const float*)d_in[0];
    const float* Wq = (const float*)d_in[1];
    // d_in[2] (W_k) intentionally unused: reference computes K with W_q
    const float* Wv = (const float*)d_in[3];
    const float* Wo = (const float*)d_in[4];
    float* out = (float*)d_out;

    float *Qb, *Vb, *Ob;
    cudaGetSymbolAddress((void**)&Qb, g_Q);
    cudaGetSymbolAddress((void**)&Vb, g_V);
    cudaGetSymbolAddress((void**)&Ob, g_O);

    cudaFuncSetAttribute(gemm_mma, cudaFuncAttributeMaxDynamicSharedMemorySize,
                         GEMM_SMEM);
    cudaFuncSetAttribute(attn_mma, cudaFuncAttributeMaxDynamicSharedMemorySize,
                         ATT_SMEM);

    dim3 gg(CDIM / 128, MTOT / 128);  // (8, 64)
    gemm_mma<<<gg, 256, GEMM_SMEM>>>(x, Wq, Qb);
    gemm_mma<<<gg, 256, GEMM_SMEM>>>(x, Wv, Vb);

    attn_mma<<<dim3(TSEQ / 128, 4 * NHEAD), 256, ATT_SMEM>>>(Qb, Vb, Ob);

    gemm_mma<<<gg, 256, GEMM_SMEM>>>(Ob, Wo, out);
}